// round 17
// baseline (speedup 1.0000x reference)
#include <cuda_runtime.h>
#include <cuda_fp16.h>
#include <cstdint>
#include <math.h>

#define BB 4
#define SS 4096
#define DD 256
#define HH 1024
// SCALE * log2(e): softmax computed in base-2 domain
#define SCL2E 0.25505654911f

// ---------------------------------------------------------------------------
// Scratch (__device__ globals; no cudaMalloc allowed)
// ---------------------------------------------------------------------------
__device__ __half g_xh[(size_t)BB * SS * DD];
__device__ float  g_h[(size_t)BB * SS * DD];
__device__ __half g_hf[(size_t)BB * SS * DD];
__device__ __half g_f1f[(size_t)BB * SS * HH];
__device__ float  g_f2[(size_t)BB * SS * DD];
__device__ __half g_w1t[(size_t)HH * DD];            // W1^T [H,D] fp16
__device__ __half g_w2t[(size_t)DD * HH];            // W2^T [D,H] fp16

// ---------------------------------------------------------------------------
// Helpers (baseline PTX only: cp.async, ldmatrix, mma.sync)
// ---------------------------------------------------------------------------
__device__ __forceinline__ uint32_t smem_u32(const void* p) {
    uint32_t a;
    asm("{ .reg .u64 t; cvta.to.shared.u64 t, %1; cvt.u32.u64 %0, t; }" : "=r"(a) : "l"(p));
    return a;
}
__device__ __forceinline__ void cpa16(uint32_t d, const void* g) {
    asm volatile("cp.async.cg.shared.global [%0], [%1], 16;" :: "r"(d), "l"(g) : "memory");
}
__device__ __forceinline__ uint32_t swz(uint32_t off) { return off ^ ((off >> 3) & 0x70); }

// Swizzle for 512B rows (256 fp16)
__device__ __forceinline__ uint32_t SWX(int row, int c) {
    return (uint32_t)(row * 512 + ((c ^ (row & 7)) << 4));
}
// Swizzle for 128B rows (64 fp16) — P tile
__device__ __forceinline__ uint32_t PSWX(int row, int c) {
    return (uint32_t)(row * 128 + ((c ^ (row & 7)) << 4));
}
__device__ __forceinline__ float ex2f(float x) {
    float y;
    asm("ex2.approx.f32 %0, %1;" : "=f"(y) : "f"(x));
    return y;
}

__device__ __forceinline__ void ldsm4(uint32_t& r0, uint32_t& r1, uint32_t& r2, uint32_t& r3,
                                      uint32_t addr) {
    asm volatile("ldmatrix.sync.aligned.m8n8.x4.shared.b16 {%0,%1,%2,%3}, [%4];"
        : "=r"(r0), "=r"(r1), "=r"(r2), "=r"(r3) : "r"(addr));
}
__device__ __forceinline__ void ldsm4t(uint32_t& r0, uint32_t& r1, uint32_t& r2, uint32_t& r3,
                                       uint32_t addr) {
    asm volatile("ldmatrix.sync.aligned.m8n8.x4.trans.shared.b16 {%0,%1,%2,%3}, [%4];"
        : "=r"(r0), "=r"(r1), "=r"(r2), "=r"(r3) : "r"(addr));
}
__device__ __forceinline__ void mma_f16(float* d, uint32_t a0, uint32_t a1, uint32_t a2,
                                        uint32_t a3, uint32_t b0, uint32_t b1) {
    asm volatile("mma.sync.aligned.m16n8k16.row.col.f32.f16.f16.f32 "
        "{%0,%1,%2,%3}, {%4,%5,%6,%7}, {%8,%9}, {%0,%1,%2,%3};"
        : "+f"(d[0]), "+f"(d[1]), "+f"(d[2]), "+f"(d[3])
        : "r"(a0), "r"(a1), "r"(a2), "r"(a3), "r"(b0), "r"(b1));
}
__device__ __forceinline__ uint32_t packh(float a, float b) {
    __half2 h = __floats2half2_rn(a, b);
    return *(uint32_t*)&h;
}

// ---------------------------------------------------------------------------
// Flash attention + fused LN1, split-K/split-N warp layout:
//   h[b,q,:] = LN( softmax(scale * x_q . x_k) @ x  +  x[q] ) ; also emit hf.
// CTA: 64 query rows, 256 threads (8 warps), 2 CTAs/SM.
// warp = (rowgrp = wid>>1 in 0..3 -> 16 rows, khalf = wid&1):
//   QK: 16 rows x 32 keys (khalf splits keys)   -> K frags halved
//   P staged in smem (64 x 64 fp16, swizzled)
//   PV: 16 rows x 128 cols (khalf splits cols)  -> V frags halved
// K-tile 64 keys double-buffered.
// smem: Q 32K | K 2x32K | P 8K | stats 1K = 105K -> 2 CTAs/SM.
// ---------------------------------------------------------------------------
#define FA_SMEM 107520

__global__ void __launch_bounds__(256, 2) flash_attn(
    const __half* __restrict__ xh, const float* __restrict__ x,
    const float* __restrict__ gamma1, const float* __restrict__ beta1,
    float* __restrict__ hout, __half* __restrict__ hfout)
{
    extern __shared__ char smem[];
    const uint32_t sb = smem_u32(smem);
    const int tid = threadIdx.x, wid = tid >> 5, lane = tid & 31;
    const int rowgrp = wid >> 1;
    const int khalf = wid & 1;
    const int m0 = blockIdx.x * 64;
    const int bz = blockIdx.y;
    const __half* qp = xh + ((size_t)bz * SS + m0) * DD;
    const __half* kp_all = xh + (size_t)bz * SS * DD;
    const uint32_t QH = sb, KB = sb + 32768, PT = sb + 98304;
    float* mx_s = (float*)(smem + 106496);   // [2][64]
    float* sm_s = (float*)(smem + 107008);   // [2][64]

    // Load Q (64 rows x 512B)
    #pragma unroll
    for (int i = 0; i < 8; i++) {
        int j = tid + i * 256;
        int row = j >> 5, c = j & 31;
        cpa16(QH + SWX(row, c), qp + row * DD + c * 8);
    }
    asm volatile("cp.async.commit_group;" ::: "memory");

    auto load_kv = [&](int t) {
        const uint32_t b = KB + (t & 1) * 32768;
        const __half* kp = kp_all + (size_t)t * 64 * DD;
        #pragma unroll
        for (int i = 0; i < 8; i++) {
            int j = tid + i * 256;
            int row = j >> 5, c = j & 31;
            cpa16(b + SWX(row, c), kp + row * DD + c * 8);
        }
        asm volatile("cp.async.commit_group;" ::: "memory");
    };

    load_kv(0);

    float O[16][4];                       // 16 n8-blocks x 128 cols per warp
    #pragma unroll
    for (int n = 0; n < 16; n++)
        #pragma unroll
        for (int q = 0; q < 4; q++) O[n][q] = 0.0f;
    float m0r = -INFINITY, m1r = -INFINITY, l0 = 0.0f, l1 = 0.0f;

    const int qrow = rowgrp * 16 + (lane & 15);
    const int qc_h = lane >> 4;
    const int krow = ((lane >> 4) << 3) + (lane & 7);
    const int kc_h = (lane >> 3) & 1;
    const int vrow = ((lane >> 3) & 1) * 8 + (lane & 7);
    const int r0 = lane >> 2;
    const int srow0 = rowgrp * 16 + r0;
    const int srow1 = srow0 + 8;

    const int T = SS / 64;
    for (int t = 0; t < T; t++) {
        if (t + 1 < T) {
            load_kv(t + 1);
            asm volatile("cp.async.wait_group 1;" ::: "memory");
        } else {
            asm volatile("cp.async.wait_group 0;" ::: "memory");
        }
        __syncthreads();                  // B1: K(t) ready; prev PV done
        const uint32_t KH = KB + (t & 1) * 32768;

        // ---- partial scores: S[16 rows, 32 keys of this khalf] ----
        float sa[4][4];
        #pragma unroll
        for (int j = 0; j < 4; j++)
            #pragma unroll
            for (int q = 0; q < 4; q++) sa[j][q] = 0.0f;

        #pragma unroll
        for (int s = 0; s < 16; s++) {
            uint32_t ah[4], bh[4][2];
            ldsm4(ah[0], ah[1], ah[2], ah[3], QH + SWX(qrow, 2 * s + qc_h));
            #pragma unroll
            for (int jj = 0; jj < 2; jj++) {
                uint32_t off = SWX(khalf * 32 + jj * 16 + krow, 2 * s + kc_h);
                ldsm4(bh[2 * jj][0], bh[2 * jj][1], bh[2 * jj + 1][0], bh[2 * jj + 1][1],
                      KH + off);
            }
            #pragma unroll
            for (int j = 0; j < 4; j++)
                mma_f16(sa[j], ah[0], ah[1], ah[2], ah[3], bh[j][0], bh[j][1]);
        }
        #pragma unroll
        for (int j = 0; j < 4; j++)
            #pragma unroll
            for (int q = 0; q < 4; q++) sa[j][q] *= SCL2E;

        // ---- partial row max (this khalf) ----
        float mx0 = -INFINITY, mx1 = -INFINITY;
        #pragma unroll
        for (int j = 0; j < 4; j++) {
            mx0 = fmaxf(mx0, fmaxf(sa[j][0], sa[j][1]));
            mx1 = fmaxf(mx1, fmaxf(sa[j][2], sa[j][3]));
        }
        mx0 = fmaxf(mx0, __shfl_xor_sync(0xffffffffu, mx0, 1));
        mx0 = fmaxf(mx0, __shfl_xor_sync(0xffffffffu, mx0, 2));
        mx1 = fmaxf(mx1, __shfl_xor_sync(0xffffffffu, mx1, 1));
        mx1 = fmaxf(mx1, __shfl_xor_sync(0xffffffffu, mx1, 2));
        if ((lane & 3) == 0) {
            mx_s[khalf * 64 + srow0] = mx0;
            mx_s[khalf * 64 + srow1] = mx1;
        }
        __syncthreads();                  // B2: partial maxes visible

        const float cm0 = fmaxf(mx_s[srow0], mx_s[64 + srow0]);
        const float cm1 = fmaxf(mx_s[srow1], mx_s[64 + srow1]);
        const float mn0 = fmaxf(m0r, cm0), mn1 = fmaxf(m1r, cm1);
        const float sc0 = ex2f(m0r - mn0), sc1 = ex2f(m1r - mn1);
        m0r = mn0; m1r = mn1;

        float ts0 = 0.0f, ts1 = 0.0f;
        #pragma unroll
        for (int j = 0; j < 4; j++) {
            sa[j][0] = ex2f(sa[j][0] - mn0);
            sa[j][1] = ex2f(sa[j][1] - mn0);
            sa[j][2] = ex2f(sa[j][2] - mn1);
            sa[j][3] = ex2f(sa[j][3] - mn1);
            ts0 += sa[j][0] + sa[j][1];
            ts1 += sa[j][2] + sa[j][3];
        }
        ts0 += __shfl_xor_sync(0xffffffffu, ts0, 1);
        ts0 += __shfl_xor_sync(0xffffffffu, ts0, 2);
        ts1 += __shfl_xor_sync(0xffffffffu, ts1, 1);
        ts1 += __shfl_xor_sync(0xffffffffu, ts1, 2);
        if ((lane & 3) == 0) {
            sm_s[khalf * 64 + srow0] = ts0;
            sm_s[khalf * 64 + srow1] = ts1;
        }
        // stage P (fp16) into smem: keys khalf*32 + j*8 + (lane&3)*2
        {
            const int co = (lane & 3) * 4;
            #pragma unroll
            for (int j = 0; j < 4; j++) {
                const int ch = khalf * 4 + j;
                uint32_t a0 = PT + (uint32_t)(srow0 * 128 + ((ch ^ (srow0 & 7)) << 4) + co);
                uint32_t a1 = PT + (uint32_t)(srow1 * 128 + ((ch ^ (srow1 & 7)) << 4) + co);
                uint32_t p0 = packh(sa[j][0], sa[j][1]);
                uint32_t p1 = packh(sa[j][2], sa[j][3]);
                asm volatile("st.shared.b32 [%0], %1;" :: "r"(a0), "r"(p0) : "memory");
                asm volatile("st.shared.b32 [%0], %1;" :: "r"(a1), "r"(p1) : "memory");
            }
        }
        __syncthreads();                  // B3: P + partial sums visible

        l0 = l0 * sc0 + sm_s[srow0] + sm_s[64 + srow0];
        l1 = l1 * sc1 + sm_s[srow1] + sm_s[64 + srow1];
        if (sc0 != 1.0f || sc1 != 1.0f) {
            #pragma unroll
            for (int n = 0; n < 16; n++) {
                O[n][0] *= sc0; O[n][1] *= sc0;
                O[n][2] *= sc1; O[n][3] *= sc1;
            }
        }

        // ---- PV: O[16 rows, cols khalf*128..] += P(64 keys) @ V ----
        #pragma unroll
        for (int ks = 0; ks < 4; ks++) {
            uint32_t pa[4];
            ldsm4(pa[0], pa[1], pa[2], pa[3],
                  PT + PSWX(rowgrp * 16 + (lane & 15), ks * 2 + (lane >> 4)));
            #pragma unroll
            for (int g = 0; g < 8; g++) {
                uint32_t v0, v1, v2, v3;
                ldsm4t(v0, v1, v2, v3,
                       KH + SWX(ks * 16 + vrow, 2 * (khalf * 8 + g) + (lane >> 4)));
                mma_f16(O[2 * g],     pa[0], pa[1], pa[2], pa[3], v0, v1);
                mma_f16(O[2 * g + 1], pa[0], pa[1], pa[2], pa[3], v2, v3);
            }
        }
        __syncthreads();                  // B4: PV done before buffer overwrite
    }

    // ---- epilogue: v = O/l + x ; LN1 with cross-khalf reduction ----
    const float i0 = 1.0f / l0, i1 = 1.0f / l1;
    const int cq = (lane & 3) * 2;
    const size_t rowA = (size_t)bz * SS + m0 + srow0;
    const size_t rowB = rowA + 8;
    const float* xr0 = x + rowA * DD + khalf * 128;
    const float* xr1 = x + rowB * DD + khalf * 128;

    float s1A = 0.f, s2A = 0.f, s1B = 0.f, s2B = 0.f;
    #pragma unroll
    for (int n = 0; n < 16; n++) {
        const int col = n * 8 + cq;
        float2 xa = *(const float2*)(xr0 + col);
        float2 xb = *(const float2*)(xr1 + col);
        O[n][0] = O[n][0] * i0 + xa.x;
        O[n][1] = O[n][1] * i0 + xa.y;
        O[n][2] = O[n][2] * i1 + xb.x;
        O[n][3] = O[n][3] * i1 + xb.y;
        s1A += O[n][0] + O[n][1];
        s2A += O[n][0] * O[n][0] + O[n][1] * O[n][1];
        s1B += O[n][2] + O[n][3];
        s2B += O[n][2] * O[n][2] + O[n][3] * O[n][3];
    }
    s1A += __shfl_xor_sync(0xffffffffu, s1A, 1);
    s1A += __shfl_xor_sync(0xffffffffu, s1A, 2);
    s2A += __shfl_xor_sync(0xffffffffu, s2A, 1);
    s2A += __shfl_xor_sync(0xffffffffu, s2A, 2);
    s1B += __shfl_xor_sync(0xffffffffu, s1B, 1);
    s1B += __shfl_xor_sync(0xffffffffu, s1B, 2);
    s2B += __shfl_xor_sync(0xffffffffu, s2B, 1);
    s2B += __shfl_xor_sync(0xffffffffu, s2B, 2);
    if ((lane & 3) == 0) {
        mx_s[khalf * 64 + srow0] = s1A;
        mx_s[khalf * 64 + srow1] = s1B;
        sm_s[khalf * 64 + srow0] = s2A;
        sm_s[khalf * 64 + srow1] = s2B;
    }
    __syncthreads();

    const float t1A = mx_s[srow0] + mx_s[64 + srow0];
    const float t2A = sm_s[srow0] + sm_s[64 + srow0];
    const float t1B = mx_s[srow1] + mx_s[64 + srow1];
    const float t2B = sm_s[srow1] + sm_s[64 + srow1];
    const float mA = t1A * (1.0f / 256.0f);
    const float invA = rsqrtf(t2A * (1.0f / 256.0f) - mA * mA + 1e-5f);
    const float mB = t1B * (1.0f / 256.0f);
    const float invB = rsqrtf(t2B * (1.0f / 256.0f) - mB * mB + 1e-5f);

    float* h0 = hout + rowA * DD + khalf * 128;
    float* h1 = hout + rowB * DD + khalf * 128;
    __half* hf0 = hfout + rowA * DD + khalf * 128;
    __half* hf1 = hfout + rowB * DD + khalf * 128;
    const float* gp = gamma1 + khalf * 128;
    const float* bp = beta1 + khalf * 128;
    #pragma unroll
    for (int n = 0; n < 16; n++) {
        const int col = n * 8 + cq;
        float2 gg = *(const float2*)(gp + col);
        float2 bb = *(const float2*)(bp + col);
        float a0 = (O[n][0] - mA) * invA * gg.x + bb.x;
        float a1 = (O[n][1] - mA) * invA * gg.y + bb.y;
        float b0 = (O[n][2] - mB) * invB * gg.x + bb.x;
        float b1 = (O[n][3] - mB) * invB * gg.y + bb.y;
        *(float2*)(h0 + col) = make_float2(a0, a1);
        *(float2*)(h1 + col) = make_float2(b0, b1);
        *(uint32_t*)(hf0 + col) = packh(a0, a1);
        *(uint32_t*)(hf1 + col) = packh(b0, b1);
    }
}

// ---------------------------------------------------------------------------
// FFN GEMM (fp16, 1-term): C[M,N] = A[M,K] * B[N,K]^T
// MODE 2: Cf f16 = relu(acc + bias)      MODE 3: C fp32 = acc + bias
// Block 128x128, K-tile 64, 8 warps (2x4), double-buffered, 2 CTAs/SM.
// ---------------------------------------------------------------------------
#define Bb 32768   // per-buffer: A 16K | B 16K
template <int MODE>
__global__ void __launch_bounds__(256, 2) gemm_ffn(
    const __half* __restrict__ A, const __half* __restrict__ B,
    float* __restrict__ C, __half* __restrict__ Cf,
    const float* __restrict__ bias, int M, int N, int K)
{
    extern __shared__ char smem[];
    const uint32_t sb = smem_u32(smem);
    const int tid = threadIdx.x, wid = tid >> 5, lane = tid & 31;
    const int m0 = blockIdx.y * 128, n0 = blockIdx.x * 128;

    const int wm = wid & 1;
    const int wn = wid >> 1;
    const int a_row = lane & 15, a_kh = lane >> 4;
    const int b_roff = ((lane >> 4) & 1) * 8 + (lane & 7), b_kh = (lane >> 3) & 1;

    float acc[4][4][4];
    #pragma unroll
    for (int i = 0; i < 4; i++)
        #pragma unroll
        for (int j = 0; j < 4; j++)
            #pragma unroll
            for (int q = 0; q < 4; q++) acc[i][j][q] = 0.0f;

    const int KT = K >> 6;

    auto load_tile = [&](int kt) {
        const uint32_t tb = sb + (kt & 1) * Bb;
        const int k0 = kt << 6;
        #pragma unroll
        for (int t = 0; t < 4; t++) {
            int id = tid + t * 256;
            int row = id >> 3, ch = id & 7;
            uint32_t so = swz((uint32_t)(row * 128 + ch * 16));
            cpa16(tb + so,         A + (size_t)(m0 + row) * K + k0 + ch * 8);
            cpa16(tb + 16384 + so, B + (size_t)(n0 + row) * K + k0 + ch * 8);
        }
        asm volatile("cp.async.commit_group;" ::: "memory");
    };

    load_tile(0);

    for (int kt = 0; kt < KT; kt++) {
        if (kt + 1 < KT) {
            load_tile(kt + 1);
            asm volatile("cp.async.wait_group 1;" ::: "memory");
        } else {
            asm volatile("cp.async.wait_group 0;" ::: "memory");
        }
        __syncthreads();

        const uint32_t tb = sb + (kt & 1) * Bb;
        #pragma unroll
        for (int s = 0; s < 4; s++) {
            uint32_t av[4][4];
            #pragma unroll
            for (int i = 0; i < 4; i++) {
                uint32_t off = swz((uint32_t)((wm * 64 + i * 16 + a_row) * 128 +
                                              (s * 2 + a_kh) * 16));
                ldsm4(av[i][0], av[i][1], av[i][2], av[i][3], tb + off);
            }
            uint32_t bv[4][2];
            #pragma unroll
            for (int jj = 0; jj < 2; jj++) {
                uint32_t off = swz((uint32_t)((wn * 32 + jj * 16 + b_roff) * 128 +
                                              (s * 2 + b_kh) * 16));
                ldsm4(bv[2 * jj][0], bv[2 * jj][1], bv[2 * jj + 1][0], bv[2 * jj + 1][1],
                      tb + 16384 + off);
            }
            #pragma unroll
            for (int i = 0; i < 4; i++)
                #pragma unroll
                for (int j = 0; j < 4; j++)
                    mma_f16(acc[i][j], av[i][0], av[i][1], av[i][2], av[i][3],
                            bv[j][0], bv[j][1]);
        }
        __syncthreads();
    }

    const int g = lane >> 2, cq = (lane & 3) * 2;
    #pragma unroll
    for (int i = 0; i < 4; i++) {
        #pragma unroll
        for (int j = 0; j < 4; j++) {
            const int row = m0 + wm * 64 + i * 16 + g;
            const int col = n0 + wn * 32 + j * 8 + cq;
            float v0 = acc[i][j][0], v1 = acc[i][j][1];
            float v2 = acc[i][j][2], v3 = acc[i][j][3];
            const float bv0 = bias[col], bv1 = bias[col + 1];
            v0 += bv0; v1 += bv1; v2 += bv0; v3 += bv1;
            size_t i0 = (size_t)row * N + col;
            size_t i1 = (size_t)(row + 8) * N + col;
            if (MODE == 2) {
                v0 = fmaxf(v0, 0.f); v1 = fmaxf(v1, 0.f);
                v2 = fmaxf(v2, 0.f); v3 = fmaxf(v3, 0.f);
                *(__half2*)(Cf + i0) = __floats2half2_rn(v0, v1);
                *(__half2*)(Cf + i1) = __floats2half2_rn(v2, v3);
            } else {
                *(float2*)(C + i0) = {v0, v1};
                *(float2*)(C + i1) = {v2, v3};
            }
        }
    }
}

// ---------------------------------------------------------------------------
// Elementwise / conversion kernels
// ---------------------------------------------------------------------------
__global__ void conv_f16(const float* __restrict__ in, __half* __restrict__ o, size_t n) {
    size_t i = ((size_t)blockIdx.x * blockDim.x + threadIdx.x) * 8;
    if (i < n) {
        float4 v0 = *(const float4*)(in + i);
        float4 v1 = *(const float4*)(in + i + 4);
        uint4 r;
        r.x = packh(v0.x, v0.y);
        r.y = packh(v0.z, v0.w);
        r.z = packh(v1.x, v1.y);
        r.w = packh(v1.z, v1.w);
        *(uint4*)(o + i) = r;
    }
}

__global__ void transpose_f16(const float* __restrict__ in, __half* __restrict__ o,
                              int R, int C) {
    __shared__ float t[32][33];
    int c = blockIdx.x * 32 + threadIdx.x;
    #pragma unroll
    for (int i = 0; i < 4; i++) {
        int r = blockIdx.y * 32 + threadIdx.y + i * 8;
        if (r < R && c < C) t[threadIdx.y + i * 8][threadIdx.x] = in[(size_t)r * C + c];
    }
    __syncthreads();
    int rr = blockIdx.y * 32 + threadIdx.x;
    #pragma unroll
    for (int i = 0; i < 4; i++) {
        int cc = blockIdx.x * 32 + threadIdx.y + i * 8;
        if (rr < R && cc < C)
            o[(size_t)cc * R + rr] = __float2half_rn(t[threadIdx.x][threadIdx.y + i * 8]);
    }
}

// out = LN(a + r) * g + be.  Warp-per-row (D=256 -> 8 fp32/lane), shuffle-only.
__global__ void add_ln(const float* __restrict__ a, const float* __restrict__ r,
                       const float* __restrict__ g, const float* __restrict__ be,
                       float* __restrict__ out, __half* __restrict__ of) {
    const int lane = threadIdx.x & 31;
    const size_t row = (size_t)blockIdx.x * 8 + (threadIdx.x >> 5);
    const size_t base = row * DD + lane * 8;

    float4 va0 = *(const float4*)(a + base);
    float4 va1 = *(const float4*)(a + base + 4);
    float4 vr0 = *(const float4*)(r + base);
    float4 vr1 = *(const float4*)(r + base + 4);
    float v[8] = {va0.x + vr0.x, va0.y + vr0.y, va0.z + vr0.z, va0.w + vr0.w,
                  va1.x + vr1.x, va1.y + vr1.y, va1.z + vr1.z, va1.w + vr1.w};

    float s = 0.f;
    #pragma unroll
    for (int i = 0; i < 8; i++) s += v[i];
    #pragma unroll
    for (int o = 16; o > 0; o >>= 1) s += __shfl_xor_sync(0xffffffffu, s, o);
    const float mean = s * (1.0f / 256.0f);

    float q = 0.f;
    #pragma unroll
    for (int i = 0; i < 8; i++) {
        v[i] -= mean;
        q += v[i] * v[i];
    }
    #pragma unroll
    for (int o = 16; o > 0; o >>= 1) q += __shfl_xor_sync(0xffffffffu, q, o);
    const float inv = rsqrtf(q * (1.0f / 256.0f) + 1e-5f);

    float4 vg0 = *(const float4*)(g + lane * 8);
    float4 vg1 = *(const float4*)(g + lane * 8 + 4);
    float4 vb0 = *(const float4*)(be + lane * 8);
    float4 vb1 = *(const float4*)(be + lane * 8 + 4);
    float res[8];
    res[0] = v[0] * inv * vg0.x + vb0.x;
    res[1] = v[1] * inv * vg0.y + vb0.y;
    res[2] = v[2] * inv * vg0.z + vb0.z;
    res[3] = v[3] * inv * vg0.w + vb0.w;
    res[4] = v[4] * inv * vg1.x + vb1.x;
    res[5] = v[5] * inv * vg1.y + vb1.y;
    res[6] = v[6] * inv * vg1.z + vb1.z;
    res[7] = v[7] * inv * vg1.w + vb1.w;

    *(float4*)(out + base)     = make_float4(res[0], res[1], res[2], res[3]);
    *(float4*)(out + base + 4) = make_float4(res[4], res[5], res[6], res[7]);
    if (of) {
        uint4 hv;
        hv.x = packh(res[0], res[1]);
        hv.y = packh(res[2], res[3]);
        hv.z = packh(res[4], res[5]);
        hv.w = packh(res[6], res[7]);
        *(uint4*)(of + base) = hv;
    }
}

// ---------------------------------------------------------------------------
// Launch
// ---------------------------------------------------------------------------
extern "C" void kernel_launch(void* const* d_in, const int* in_sizes, int n_in,
                              void* d_out, int out_size) {
    const float* x      = (const float*)d_in[0];
    const float* gamma1 = (const float*)d_in[1];
    const float* beta1  = (const float*)d_in[2];
    const float* W1     = (const float*)d_in[3];
    const float* b1     = (const float*)d_in[4];
    const float* W2     = (const float*)d_in[5];
    const float* b2     = (const float*)d_in[6];
    const float* gamma2 = (const float*)d_in[7];
    const float* beta2  = (const float*)d_in[8];
    float* out = (float*)d_out;

    float *h, *f2;
    __half *xh, *hf, *f1f, *w1t, *w2t;
    cudaGetSymbolAddress((void**)&xh, g_xh);
    cudaGetSymbolAddress((void**)&h, g_h);
    cudaGetSymbolAddress((void**)&hf, g_hf);
    cudaGetSymbolAddress((void**)&f1f, g_f1f);
    cudaGetSymbolAddress((void**)&f2, g_f2);
    cudaGetSymbolAddress((void**)&w1t, g_w1t);
    cudaGetSymbolAddress((void**)&w2t, g_w2t);

    const int SMEM = 2 * Bb;   // 65536
    cudaFuncSetAttribute(gemm_ffn<2>, cudaFuncAttributeMaxDynamicSharedMemorySize, SMEM);
    cudaFuncSetAttribute(gemm_ffn<3>, cudaFuncAttributeMaxDynamicSharedMemorySize, SMEM);
    cudaFuncSetAttribute(flash_attn, cudaFuncAttributeMaxDynamicSharedMemorySize, FA_SMEM);

    const int rows = BB * SS;

    // conversions
    conv_f16<<<(BB * SS * DD / 8 + 255) / 256, 256>>>(x, xh, (size_t)BB * SS * DD);
    transpose_f16<<<dim3(HH / 32, DD / 32), dim3(32, 8)>>>(W1, w1t, DD, HH);
    transpose_f16<<<dim3(DD / 32, HH / 32), dim3(32, 8)>>>(W2, w2t, HH, DD);

    // 1-4) fused attention + LN1: h = LN(softmax(scale x x^T) x + x), hf = f16(h)
    flash_attn<<<dim3(SS / 64, BB), 256, FA_SMEM>>>(xh, x, gamma1, beta1, h, hf);

    // 5) f1 = relu(h @ W1 + b1) -> f16
    gemm_ffn<2><<<dim3(HH / 128, rows / 128), 256, SMEM>>>(
        hf, w1t, nullptr, f1f, b1, rows, HH, DD);

    // 6) f2 = f1 @ W2 + b2
    gemm_ffn<3><<<dim3(DD / 128, rows / 128), 256, SMEM>>>(
        f1f, w2t, f2, nullptr, b2, rows, DD, HH);

    // 7) out = LN(f2 + h)
    add_ln<<<rows / 8, 256>>>(f2, h, gamma2, beta2, out, nullptr);
}